// round 16
// baseline (speedup 1.0000x reference)
#include <cuda_runtime.h>
#include <cstdint>

typedef unsigned long long ull_t;

// Packed fp32x2 FMA (Blackwell): d = a*b + c per 32-bit lane.
#define FMA2(d, a, b, c) \
    asm("fma.rn.f32x2 %0, %1, %2, %3;" : "=l"(d) : "l"(a), "l"(b), "l"(c))

// Splat one fp32 into both halves of a 64-bit reg pair.
#define SPLAT(s, f) \
    asm("mov.b64 %0, {%1, %1};" : "=l"(s) : "f"(f))

// Streaming (evict-first) 64-bit global store: output is write-once.
#define STG_CS64(p, v) \
    asm volatile("st.global.cs.b64 [%0], %1;" :: "l"(p), "l"(v) : "memory")

// 8-byte async copy global->shared with zero-fill when sz==0.
#define CP_ASYNC8(dst, src, sz) \
    asm volatile("cp.async.ca.shared.global [%0], [%1], 8, %2;" \
                 :: "r"(dst), "l"(src), "r"(sz) : "memory")

// Combined weight: Wc[k][ch] = sum_e gcn_w[ch][e] * conv_w[e][k].
__device__ float g_wc[12 * 192];

// One warp per output element (2304 warps); 288x256 measured-best PDL shape.
__global__ void wc_kernel(const float* __restrict__ conv_w,
                          const float* __restrict__ gcn_w) {
    const int w    = (blockIdx.x * blockDim.x + threadIdx.x) >> 5;  // 0..2303
    const int lane = threadIdx.x & 31;
    if (w < 2304) {
        const int k  = w % 12;
        const int ch = w / 12;
        float s = 0.f;
#pragma unroll
        for (int j = 0; j < 6; j++) {
            const int e = lane + 32 * j;
            s += gcn_w[ch * 192 + e] * conv_w[e * 12 + k];
        }
#pragma unroll
        for (int off = 16; off > 0; off >>= 1)
            s += __shfl_xor_sync(0xffffffffu, s, off);
        if (lane == 0) g_wc[k * 192 + ch] = s;
    }
    cudaTriggerProgrammaticLaunchCompletion();
}

// 256x256 patch grid; deg in {3,4,5} only -> select-based D^{-1/2} (no MUFU).
__device__ __forceinline__ float dinv_of(int gi, int gj) {
    const int deg = 1 + (gi > 0) + (gi < 255) + (gj > 0) + (gj < 255);
    return deg == 4 ? 0.5f
         : (deg == 3 ? 0.5773502691896258f : 0.4472135954999579f);
}

// Tile: 16x16 nodes (256), halo 18x18 (324). 384 threads, 3 CTAs/SM.
// R11 skeleton (measured best) + explicit depth-1 prefetch pipeline in
// phase 3 to hide the 29-cyc broadcast-LDS latency per node.
__global__ __launch_bounds__(384, 3)
void fused_kernel(const float* __restrict__ x,
                  const float* __restrict__ bias,
                  float* __restrict__ out) {
    __shared__ float sp[324 * 12];    // raw patch values per halo node
    __shared__ float accs[256 * 12];  // normalized stencil sum per node

    const int t    = threadIdx.x;
    const int lane = t & 31;
    const int wid  = t >> 5;     // 0..11
    const int b    = blockIdx.z;
    const int ti   = blockIdx.y; // 0..15
    const int tj   = blockIdx.x; // 0..15

    const unsigned sp_sa = (unsigned)__cvta_generic_to_shared(sp);

    // ---- phase 1: async-stage raw patches for 18x18 halo (648 tasks) ----
#pragma unroll
    for (int task = t; task < 648; task += 384) {
        const int hn = task >> 1;        // halo node 0..323
        const int u  = task & 1;         // pixel row within patch
        const int li = hn / 18, lj = hn % 18;
        const int gi = ti * 16 - 1 + li;
        const int gj = tj * 16 - 1 + lj;
        const bool in = (gi >= 0 && gi < 256 && gj >= 0 && gj < 256);
        const int sz  = in ? 8 : 0;      // 0 => zero-fill 8 bytes
        const int cgi = min(max(gi, 0), 255);
        const int cgj = min(max(gj, 0), 255);
#pragma unroll
        for (int c = 0; c < 3; c++) {
            const float* src = x
                + (((size_t)b * 3 + c) * 512 + (size_t)(cgi * 2 + u)) * 512
                + (size_t)(cgj * 2);
            const unsigned dst = sp_sa + (unsigned)(hn * 12 + c * 4 + u * 2) * 4u;
            CP_ASYNC8(dst, src, sz);
        }
    }
    asm volatile("cp.async.commit_group;" ::: "memory");

    // ---- wait for wc_kernel (PDL); load weights while copies fly ----
    cudaGridDependencySynchronize();

    const int g  = wid >> 2;             // channel group 0..2
    const int r  = wid & 3;              // row-quad 0..3 (rows 4r..4r+3)
    const int ch = 64 * g + 2 * lane;
    ull_t w[12];
#pragma unroll
    for (int k = 0; k < 12; k++)
        w[k] = *reinterpret_cast<const ull_t*>(&g_wc[k * 192 + ch]);
    const ull_t bb = *reinterpret_cast<const ull_t*>(&bias[ch]);

    asm volatile("cp.async.wait_group 0;" ::: "memory");
    __syncthreads();

    // ---- phase 2: normalized 5-point stencil; 768 tasks (node, quad) ----
#pragma unroll
    for (int task = t; task < 768; task += 384) {
        const int node = task & 255;
        const int qq   = task >> 8;      // 0..2
        const int li = node >> 4, lj = node & 15;
        const int gi = ti * 16 + li, gj = tj * 16 + lj;
        const float dc = dinv_of(gi, gj);          // == dv_dst
        const float du = dinv_of(gi - 1, gj);
        const float dd = dinv_of(gi + 1, gj);
        const float dl = dinv_of(gi, gj - 1);
        const float dr = dinv_of(gi, gj + 1);
        const int c0 = ((li + 1) * 18 + (lj + 1)) * 12 + 4 * qq;
        const float4 vc = *reinterpret_cast<const float4*>(&sp[c0]);
        const float4 vu = *reinterpret_cast<const float4*>(&sp[c0 - 18 * 12]);
        const float4 vd = *reinterpret_cast<const float4*>(&sp[c0 + 18 * 12]);
        const float4 vl = *reinterpret_cast<const float4*>(&sp[c0 - 12]);
        const float4 vr = *reinterpret_cast<const float4*>(&sp[c0 + 12]);
        *reinterpret_cast<float4*>(&accs[node * 12 + 4 * qq]) = make_float4(
            dc * (dc * vc.x + du * vu.x + dd * vd.x + dl * vl.x + dr * vr.x),
            dc * (dc * vc.y + du * vu.y + dd * vd.y + dl * vl.y + dr * vr.y),
            dc * (dc * vc.z + du * vu.z + dd * vd.z + dl * vl.z + dr * vr.z),
            dc * (dc * vc.w + du * vu.w + dd * vd.w + dl * vl.w + dr * vr.w));
    }
    __syncthreads();

    // ---- phase 3: warp = (group g, row-quad r); 64 nodes, 64 ch each.
    // Depth-1 software pipeline: preload node n+1's acc while FMA-ing node n.
    const float* ac = &accs[(r * 64) * 12];
    float* op = out + (size_t)b * 65536 * 192
              + (size_t)((ti * 16 + 4 * r) * 256 + tj * 16) * 192 + (size_t)ch;

    float4 p0 = *reinterpret_cast<const float4*>(ac);
    float4 p1 = *reinterpret_cast<const float4*>(ac + 4);
    float4 p2 = *reinterpret_cast<const float4*>(ac + 8);

#pragma unroll 2
    for (int n = 0; n < 64; n++) {
        const float4 a0 = p0, a1 = p1, a2 = p2;
        if (n < 63) {
            const float* nxt = ac + (n + 1) * 12;
            p0 = *reinterpret_cast<const float4*>(nxt);
            p1 = *reinterpret_cast<const float4*>(nxt + 4);
            p2 = *reinterpret_cast<const float4*>(nxt + 8);
        }
        const float av[12] = {a0.x, a0.y, a0.z, a0.w,
                              a1.x, a1.y, a1.z, a1.w,
                              a2.x, a2.y, a2.z, a2.w};
        ull_t acc = bb;
#pragma unroll
        for (int k = 0; k < 12; k++) {
            ull_t s;
            SPLAT(s, av[k]);
            FMA2(acc, s, w[k], acc);
        }
        // node n -> tile row 4r + (n>>4), col (n&15)
        STG_CS64(op + (size_t)(n >> 4) * (256 * 192) + (size_t)(n & 15) * 192,
                 acc);
    }
}

extern "C" void kernel_launch(void* const* d_in, const int* in_sizes, int n_in,
                              void* d_out, int out_size) {
    const float* x      = (const float*)d_in[0];   // [4,3,512,512]
    const float* conv_w = (const float*)d_in[1];   // [192,3,2,2]
    const float* gcn_w  = (const float*)d_in[2];   // [192,192]
    const float* gcn_b  = (const float*)d_in[3];   // [192]

    wc_kernel<<<288, 256>>>(conv_w, gcn_w);        // measured-best PDL shape

    // PDL: fused starts while wc runs; gridDependencySynchronize gates g_wc.
    cudaLaunchConfig_t cfg = {};
    cfg.gridDim  = dim3(16, 16, 4);   // (tile_j, tile_i, batch)
    cfg.blockDim = dim3(384, 1, 1);
    cfg.dynamicSmemBytes = 0;
    cfg.stream = 0;
    cudaLaunchAttribute attr[1];
    attr[0].id = cudaLaunchAttributeProgrammaticStreamSerialization;
    attr[0].val.programmaticStreamSerializationAllowed = 1;
    cfg.attrs = attr;
    cfg.numAttrs = 1;
    cudaError_t e = cudaLaunchKernelEx(&cfg, fused_kernel, x, gcn_b,
                                       (float*)d_out);
    if (e != cudaSuccess) {
        dim3 grid(16, 16, 4);
        fused_kernel<<<grid, 384>>>(x, gcn_b, (float*)d_out);
    }
}

// round 17
// speedup vs baseline: 1.5017x; 1.5017x over previous
#include <cuda_runtime.h>
#include <cstdint>

typedef unsigned long long ull_t;

// Packed fp32x2 FMA (Blackwell): d = a*b + c per 32-bit lane.
#define FMA2(d, a, b, c) \
    asm("fma.rn.f32x2 %0, %1, %2, %3;" : "=l"(d) : "l"(a), "l"(b), "l"(c))

// Splat one fp32 into both halves of a 64-bit reg pair.
#define SPLAT(s, f) \
    asm("mov.b64 %0, {%1, %1};" : "=l"(s) : "f"(f))

// Streaming (evict-first) 64-bit global store: output is write-once.
#define STG_CS64(p, v) \
    asm volatile("st.global.cs.b64 [%0], %1;" :: "l"(p), "l"(v) : "memory")

// 8-byte async copy global->shared with zero-fill when sz==0.
#define CP_ASYNC8(dst, src, sz) \
    asm volatile("cp.async.ca.shared.global [%0], [%1], 8, %2;" \
                 :: "r"(dst), "l"(src), "r"(sz) : "memory")

// Combined weight: Wc[k][ch] = sum_e gcn_w[ch][e] * conv_w[e][k].
__device__ float g_wc[12 * 192];

// One warp per output element (2304 warps); 288x256 measured-best PDL shape.
__global__ void wc_kernel(const float* __restrict__ conv_w,
                          const float* __restrict__ gcn_w) {
    const int w    = (blockIdx.x * blockDim.x + threadIdx.x) >> 5;  // 0..2303
    const int lane = threadIdx.x & 31;
    if (w < 2304) {
        const int k  = w % 12;
        const int ch = w / 12;
        float s = 0.f;
#pragma unroll
        for (int j = 0; j < 6; j++) {
            const int e = lane + 32 * j;
            s += gcn_w[ch * 192 + e] * conv_w[e * 12 + k];
        }
#pragma unroll
        for (int off = 16; off > 0; off >>= 1)
            s += __shfl_xor_sync(0xffffffffu, s, off);
        if (lane == 0) g_wc[k * 192 + ch] = s;
    }
    cudaTriggerProgrammaticLaunchCompletion();
}

// 256x256 patch grid; deg in {3,4,5} only -> select-based D^{-1/2} (no MUFU).
__device__ __forceinline__ float dinv_of(int gi, int gj) {
    const int deg = 1 + (gi > 0) + (gi < 255) + (gj > 0) + (gj < 255);
    return deg == 4 ? 0.5f
         : (deg == 3 ? 0.5773502691896258f : 0.4472135954999579f);
}

// Tile: 16x16 nodes (256), halo 18x18 (324). 384 threads, 3 CTAs/SM.
// R11 configuration — measured local optimum (38.66us total / 36.77us fused).
__global__ __launch_bounds__(384, 3)
void fused_kernel(const float* __restrict__ x,
                  const float* __restrict__ bias,
                  float* __restrict__ out) {
    __shared__ float sp[324 * 12];    // raw patch values per halo node
    __shared__ float accs[256 * 12];  // normalized stencil sum per node

    const int t    = threadIdx.x;
    const int lane = t & 31;
    const int wid  = t >> 5;     // 0..11
    const int b    = blockIdx.z;
    const int ti   = blockIdx.y; // 0..15
    const int tj   = blockIdx.x; // 0..15

    const unsigned sp_sa = (unsigned)__cvta_generic_to_shared(sp);

    // ---- phase 1: async-stage raw patches for 18x18 halo (648 tasks) ----
#pragma unroll
    for (int task = t; task < 648; task += 384) {
        const int hn = task >> 1;        // halo node 0..323
        const int u  = task & 1;         // pixel row within patch
        const int li = hn / 18, lj = hn % 18;
        const int gi = ti * 16 - 1 + li;
        const int gj = tj * 16 - 1 + lj;
        const bool in = (gi >= 0 && gi < 256 && gj >= 0 && gj < 256);
        const int sz  = in ? 8 : 0;      // 0 => zero-fill 8 bytes
        const int cgi = min(max(gi, 0), 255);
        const int cgj = min(max(gj, 0), 255);
#pragma unroll
        for (int c = 0; c < 3; c++) {
            const float* src = x
                + (((size_t)b * 3 + c) * 512 + (size_t)(cgi * 2 + u)) * 512
                + (size_t)(cgj * 2);
            const unsigned dst = sp_sa + (unsigned)(hn * 12 + c * 4 + u * 2) * 4u;
            CP_ASYNC8(dst, src, sz);
        }
    }
    asm volatile("cp.async.commit_group;" ::: "memory");

    // ---- wait for wc_kernel (PDL); load weights while copies fly ----
    cudaGridDependencySynchronize();

    const int g  = wid >> 2;             // channel group 0..2
    const int r  = wid & 3;              // row-quad 0..3 (rows 4r..4r+3)
    const int ch = 64 * g + 2 * lane;
    ull_t w[12];
#pragma unroll
    for (int k = 0; k < 12; k++)
        w[k] = *reinterpret_cast<const ull_t*>(&g_wc[k * 192 + ch]);
    const ull_t bb = *reinterpret_cast<const ull_t*>(&bias[ch]);

    asm volatile("cp.async.wait_group 0;" ::: "memory");
    __syncthreads();

    // ---- phase 2: normalized 5-point stencil; 768 tasks (node, quad) ----
#pragma unroll
    for (int task = t; task < 768; task += 384) {
        const int node = task & 255;
        const int qq   = task >> 8;      // 0..2
        const int li = node >> 4, lj = node & 15;
        const int gi = ti * 16 + li, gj = tj * 16 + lj;
        const float dc = dinv_of(gi, gj);          // == dv_dst
        const float du = dinv_of(gi - 1, gj);
        const float dd = dinv_of(gi + 1, gj);
        const float dl = dinv_of(gi, gj - 1);
        const float dr = dinv_of(gi, gj + 1);
        const int c0 = ((li + 1) * 18 + (lj + 1)) * 12 + 4 * qq;
        const float4 vc = *reinterpret_cast<const float4*>(&sp[c0]);
        const float4 vu = *reinterpret_cast<const float4*>(&sp[c0 - 18 * 12]);
        const float4 vd = *reinterpret_cast<const float4*>(&sp[c0 + 18 * 12]);
        const float4 vl = *reinterpret_cast<const float4*>(&sp[c0 - 12]);
        const float4 vr = *reinterpret_cast<const float4*>(&sp[c0 + 12]);
        *reinterpret_cast<float4*>(&accs[node * 12 + 4 * qq]) = make_float4(
            dc * (dc * vc.x + du * vu.x + dd * vd.x + dl * vl.x + dr * vr.x),
            dc * (dc * vc.y + du * vu.y + dd * vd.y + dl * vl.y + dr * vr.y),
            dc * (dc * vc.z + du * vu.z + dd * vd.z + dl * vl.z + dr * vr.z),
            dc * (dc * vc.w + du * vu.w + dd * vd.w + dl * vl.w + dr * vr.w));
    }
    __syncthreads();

    // ---- phase 3: warp = (group g, row-quad r); 64 nodes, 64 ch each ----
    const float* ac = &accs[(r * 64) * 12];
    float* op = out + (size_t)b * 65536 * 192
              + (size_t)((ti * 16 + 4 * r) * 256 + tj * 16) * 192 + (size_t)ch;

#pragma unroll
    for (int ii = 0; ii < 4; ii++) {
        const float* arow = ac + ii * 16 * 12;
        float* orow = op + (size_t)ii * 256 * 192;
#pragma unroll 4
        for (int j = 0; j < 16; j++) {
            const float4 a0 = *reinterpret_cast<const float4*>(arow + j * 12);
            const float4 a1 = *reinterpret_cast<const float4*>(arow + j * 12 + 4);
            const float4 a2 = *reinterpret_cast<const float4*>(arow + j * 12 + 8);
            const float av[12] = {a0.x, a0.y, a0.z, a0.w,
                                  a1.x, a1.y, a1.z, a1.w,
                                  a2.x, a2.y, a2.z, a2.w};
            ull_t acc = bb;
#pragma unroll
            for (int k = 0; k < 12; k++) {
                ull_t s;
                SPLAT(s, av[k]);
                FMA2(acc, s, w[k], acc);
            }
            STG_CS64(orow + (size_t)j * 192, acc);
        }
    }
}

extern "C" void kernel_launch(void* const* d_in, const int* in_sizes, int n_in,
                              void* d_out, int out_size) {
    const float* x      = (const float*)d_in[0];   // [4,3,512,512]
    const float* conv_w = (const float*)d_in[1];   // [192,3,2,2]
    const float* gcn_w  = (const float*)d_in[2];   // [192,192]
    const float* gcn_b  = (const float*)d_in[3];   // [192]

    wc_kernel<<<288, 256>>>(conv_w, gcn_w);        // measured-best PDL shape

    // PDL: fused starts while wc runs; gridDependencySynchronize gates g_wc.
    cudaLaunchConfig_t cfg = {};
    cfg.gridDim  = dim3(16, 16, 4);   // (tile_j, tile_i, batch)
    cfg.blockDim = dim3(384, 1, 1);
    cfg.dynamicSmemBytes = 0;
    cfg.stream = 0;
    cudaLaunchAttribute attr[1];
    attr[0].id = cudaLaunchAttributeProgrammaticStreamSerialization;
    attr[0].val.programmaticStreamSerializationAllowed = 1;
    cfg.attrs = attr;
    cfg.numAttrs = 1;
    cudaError_t e = cudaLaunchKernelEx(&cfg, fused_kernel, x, gcn_b,
                                       (float*)d_out);
    if (e != cudaSuccess) {
        dim3 grid(16, 16, 4);
        fused_kernel<<<grid, 384>>>(x, gcn_b, (float*)d_out);
    }
}